// round 8
// baseline (speedup 1.0000x reference)
#include <cuda_runtime.h>
#include <cstdint>

#define B_  32
#define S_  2048
#define C_  1024
#define G_  16
#define K_  256

__device__ float g_norms[B_ * G_ * S_];   // (B*g, S) row-major

// ---------------------------------------------------------------------------
// K1 (fused): sum-of-squares per (b,s,group) AND zero-fill of out.
// 8 bs-rows per block, 256 threads; loads and zero-stores are independent,
// so read and write streams overlap (measured 6.26 TB/s aggregate; ~98% of
// the 512MB floor). Do not touch.
// ---------------------------------------------------------------------------
__global__ __launch_bounds__(256) void k_norms_zero(const float* __restrict__ x,
                                                    float* __restrict__ out) {
    const int base_bs = blockIdx.x << 3;
    const int t = threadIdx.x;

    float4 v[8];
    #pragma unroll
    for (int r = 0; r < 8; r++)
        v[r] = __ldcs(reinterpret_cast<const float4*>(
                          x + (size_t)(base_bs + r) * C_) + t);

    const float4 z = make_float4(0.f, 0.f, 0.f, 0.f);
    #pragma unroll
    for (int r = 0; r < 8; r++)
        __stcs(reinterpret_cast<float4*>(
                   out + (size_t)(base_bs + r) * C_) + t, z);

    #pragma unroll
    for (int r = 0; r < 8; r++) {
        float ss = v[r].x * v[r].x + v[r].y * v[r].y
                 + v[r].z * v[r].z + v[r].w * v[r].w;
        #pragma unroll
        for (int off = 8; off > 0; off >>= 1)
            ss += __shfl_down_sync(0xffffffffu, ss, off, 16);
        if ((t & 15) == 0) {
            const int bs = base_bs + r;
            const int b  = bs >> 11;
            const int s  = bs & (S_ - 1);
            g_norms[((b << 4) + (t >> 4)) * S_ + s] = ss;
        }
    }
}

// ---------------------------------------------------------------------------
// K2 (fused select + apply), 1024 threads: per (b,g) row, 4-pass radix
// select for the exact Kth-largest (monotone uint encoding; 8 replicated
// histograms, warps interleave copies via w&7), exact-K index list in smem,
// then direct gather-copy of the 256 selected 64-channel chunks.
// ---------------------------------------------------------------------------
__global__ __launch_bounds__(1024) void k_select_apply(const float* __restrict__ x,
                                                       float* __restrict__ out) {
    __shared__ unsigned int vals[S_];
    __shared__ int hist[8][256];
    __shared__ int sh_k;
    __shared__ unsigned int sh_prefix;
    __shared__ int nsel;
    __shared__ unsigned short sel[K_];

    const int row = blockIdx.x;             // b*16 + g
    const int b   = row >> 4;
    const int g   = row & 15;
    const int tid = threadIdx.x;
    const int w   = (tid >> 5) & 7;         // histogram copy (4 warps share)
    const float* nr = g_norms + (size_t)row * S_;

    #pragma unroll
    for (int i = tid; i < S_; i += 1024)
        vals[i] = __float_as_uint(nr[i]);
    if (tid == 0) { sh_k = K_; sh_prefix = 0u; nsel = 0; }
    if (tid < 256) {
        #pragma unroll
        for (int c = 0; c < 8; c++) hist[c][tid] = 0;
    }
    __syncthreads();

    int k = K_;
    unsigned int prefix = 0u;
    #pragma unroll
    for (int shift = 24; shift >= 0; shift -= 8) {
        if (shift == 24) {
            #pragma unroll
            for (int i = tid; i < S_; i += 1024)
                atomicAdd(&hist[w][vals[i] >> 24], 1);
        } else {
            const unsigned int pmask = 0xFFFFFFFFu << (shift + 8);
            #pragma unroll
            for (int i = tid; i < S_; i += 1024) {
                const unsigned int u = vals[i];
                if ((u & pmask) == prefix)
                    atomicAdd(&hist[w][(u >> shift) & 255], 1);
            }
        }
        __syncthreads();

        if (tid < 32) {
            const int binbase = 255 - tid * 8;  // lane 0 owns top bins
            int bc[8];
            int c = 0;
            #pragma unroll
            for (int j = 0; j < 8; j++) {
                int h = 0;
                #pragma unroll
                for (int cp = 0; cp < 8; cp++) h += hist[cp][binbase - j];
                bc[j] = h;
                c += h;
            }
            int inc = c;
            #pragma unroll
            for (int off = 1; off < 32; off <<= 1) {
                const int nth = __shfl_up_sync(0xffffffffu, inc, off);
                if (tid >= off) inc += nth;
            }
            const int pre = inc - c;
            const bool hit = (pre < k) && (pre + c >= k);
            const unsigned int bal = __ballot_sync(0xffffffffu, hit);
            if (tid == (__ffs(bal) - 1)) {
                int cum = pre;
                #pragma unroll
                for (int j = 0; j < 8; j++) {
                    if (cum + bc[j] >= k) {
                        sh_k = k - cum;
                        sh_prefix = prefix |
                            ((unsigned int)(binbase - j) << shift);
                        break;
                    }
                    cum += bc[j];
                }
            }
        }
        __syncthreads();
        k = sh_k;
        prefix = sh_prefix;
        if (shift > 0) {
            if (tid < 256) {
                #pragma unroll
                for (int c = 0; c < 8; c++) hist[c][tid] = 0;
            }
            __syncthreads();
        }
    }

    const float thr = __uint_as_float(prefix);  // exact Kth largest

    // Exact-K index list: strictly-greater first, then tie fill.
    #pragma unroll
    for (int i = tid; i < S_; i += 1024) {
        if (__uint_as_float(vals[i]) > thr) {
            const int p = atomicAdd(&nsel, 1);
            sel[p] = (unsigned short)i;
        }
    }
    __syncthreads();
    #pragma unroll
    for (int i = tid; i < S_; i += 1024) {
        if (__uint_as_float(vals[i]) == thr) {
            const int p = atomicAdd(&nsel, 1);
            if (p < K_) sel[p] = (unsigned short)i;
        }
    }
    __syncthreads();

    // Copy: 64 subgroups x 16 lanes; each lane one float4 of the 64-channel
    // chunk; 64 positions per iteration, 4 iterations, front-batched.
    const int sub  = tid >> 4;   // 0..63
    const int lane = tid & 15;   // 0..15
    const float* xb = x   + (size_t)b * S_ * C_ + g * 64;
    float*       ob = out + (size_t)b * S_ * C_ + g * 64;

    int si[4];
    float4 v[4];
    #pragma unroll
    for (int it = 0; it < 4; it++)
        si[it] = sel[it * 64 + sub];
    #pragma unroll
    for (int it = 0; it < 4; it++)
        v[it] = __ldcs(reinterpret_cast<const float4*>(
                           xb + (size_t)si[it] * C_) + lane);
    #pragma unroll
    for (int it = 0; it < 4; it++)
        reinterpret_cast<float4*>(ob + (size_t)si[it] * C_)[lane] = v[it];
}

extern "C" void kernel_launch(void* const* d_in, const int* in_sizes, int n_in,
                              void* d_out, int out_size) {
    const float* x = (const float*)d_in[0];
    float* out = (float*)d_out;
    k_norms_zero  <<<(B_ * S_) / 8, 256>>>(x, out);
    k_select_apply<<<B_ * G_, 1024>>>(x, out);
}

// round 9
// speedup vs baseline: 1.0003x; 1.0003x over previous
#include <cuda_runtime.h>
#include <cstdint>

#define B_  32
#define S_  2048
#define C_  1024
#define G_  16
#define K_  256

__device__ float          g_norms[B_ * G_ * S_];   // (B*g, S)
__device__ unsigned short g_sel  [B_ * G_ * K_];   // selected s per (b,g)

// ---------------------------------------------------------------------------
// K1 (fused): sum-of-squares per (b,s,group) AND zero-fill of out.
// 8 bs-rows per block, 256 threads; loads and zero-stores independent.
// x loads use default policy (not streaming) so L2 retains recent x for
// k_copy's gather.
// ---------------------------------------------------------------------------
__global__ __launch_bounds__(256) void k_norms_zero(const float* __restrict__ x,
                                                    float* __restrict__ out) {
    const int base_bs = blockIdx.x << 3;
    const int t = threadIdx.x;

    float4 v[8];
    #pragma unroll
    for (int r = 0; r < 8; r++)
        v[r] = reinterpret_cast<const float4*>(
                   x + (size_t)(base_bs + r) * C_)[t];

    const float4 z = make_float4(0.f, 0.f, 0.f, 0.f);
    #pragma unroll
    for (int r = 0; r < 8; r++)
        __stcs(reinterpret_cast<float4*>(
                   out + (size_t)(base_bs + r) * C_) + t, z);

    #pragma unroll
    for (int r = 0; r < 8; r++) {
        float ss = v[r].x * v[r].x + v[r].y * v[r].y
                 + v[r].z * v[r].z + v[r].w * v[r].w;
        #pragma unroll
        for (int off = 8; off > 0; off >>= 1)
            ss += __shfl_down_sync(0xffffffffu, ss, off, 16);
        if ((t & 15) == 0) {
            const int bs = base_bs + r;
            const int b  = bs >> 11;
            const int s  = bs & (S_ - 1);
            g_norms[((b << 4) + (t >> 4)) * S_ + s] = ss;
        }
    }
}

// ---------------------------------------------------------------------------
// K2: radix select only. Exact Kth-largest per row (monotone uint encoding,
// per-warp replicated histograms), exact-K index list with tie fill, written
// to g_sel. 512 blocks x 256 threads.
// ---------------------------------------------------------------------------
__global__ __launch_bounds__(256) void k_select() {
    __shared__ unsigned int vals[S_];
    __shared__ int hist[8][256];
    __shared__ int sh_k;
    __shared__ unsigned int sh_prefix;
    __shared__ int nsel;

    const int row = blockIdx.x;             // b*16 + g
    const int tid = threadIdx.x;
    const int w   = tid >> 5;
    const float* nr = g_norms + (size_t)row * S_;

    #pragma unroll
    for (int i = tid; i < S_; i += 256)
        vals[i] = __float_as_uint(nr[i]);
    if (tid == 0) { sh_k = K_; sh_prefix = 0u; nsel = 0; }
    #pragma unroll
    for (int c = 0; c < 8; c++) hist[c][tid] = 0;
    __syncthreads();

    int k = K_;
    unsigned int prefix = 0u;
    #pragma unroll
    for (int shift = 24; shift >= 0; shift -= 8) {
        if (shift == 24) {
            #pragma unroll
            for (int i = tid; i < S_; i += 256)
                atomicAdd(&hist[w][vals[i] >> 24], 1);
        } else {
            const unsigned int pmask = 0xFFFFFFFFu << (shift + 8);
            #pragma unroll
            for (int i = tid; i < S_; i += 256) {
                const unsigned int u = vals[i];
                if ((u & pmask) == prefix)
                    atomicAdd(&hist[w][(u >> shift) & 255], 1);
            }
        }
        __syncthreads();

        if (tid < 32) {
            const int binbase = 255 - tid * 8;  // lane 0 owns top bins
            int bc[8];
            int c = 0;
            #pragma unroll
            for (int j = 0; j < 8; j++) {
                int h = 0;
                #pragma unroll
                for (int cp = 0; cp < 8; cp++) h += hist[cp][binbase - j];
                bc[j] = h;
                c += h;
            }
            int inc = c;
            #pragma unroll
            for (int off = 1; off < 32; off <<= 1) {
                const int nth = __shfl_up_sync(0xffffffffu, inc, off);
                if (tid >= off) inc += nth;
            }
            const int pre = inc - c;
            const bool hit = (pre < k) && (pre + c >= k);
            const unsigned int bal = __ballot_sync(0xffffffffu, hit);
            if (tid == (__ffs(bal) - 1)) {
                int cum = pre;
                #pragma unroll
                for (int j = 0; j < 8; j++) {
                    if (cum + bc[j] >= k) {
                        sh_k = k - cum;
                        sh_prefix = prefix |
                            ((unsigned int)(binbase - j) << shift);
                        break;
                    }
                    cum += bc[j];
                }
            }
        }
        __syncthreads();
        k = sh_k;
        prefix = sh_prefix;
        if (shift > 0) {
            #pragma unroll
            for (int c = 0; c < 8; c++) hist[c][tid] = 0;
            __syncthreads();
        }
    }

    const float thr = __uint_as_float(prefix);  // exact Kth largest
    unsigned short* srow = g_sel + (size_t)row * K_;

    #pragma unroll
    for (int i = tid; i < S_; i += 256) {
        if (__uint_as_float(vals[i]) > thr) {
            const int p = atomicAdd(&nsel, 1);
            srow[p] = (unsigned short)i;
        }
    }
    __syncthreads();
    #pragma unroll
    for (int i = tid; i < S_; i += 256) {
        if (__uint_as_float(vals[i]) == thr) {
            const int p = atomicAdd(&nsel, 1);
            if (p < K_) srow[p] = (unsigned short)i;
        }
    }
}

// ---------------------------------------------------------------------------
// K3: barrier-free wide gather-copy of the 131072 selected 64-channel chunks.
// 1024 blocks x 256 threads; each thread: 8 index loads -> 8 gathers ->
// 8 stores, all front-batched (MLP=8, k_norms-proven shape).
// Chunk c (0..131071): row = c>>8 -> (b,g); slot = c&255.
// Block handles 128 chunks: 16 subgroups x 8 chunks; lane = tid&15 moves
// one float4 of the 64-channel chunk.
// ---------------------------------------------------------------------------
__global__ __launch_bounds__(256) void k_copy(const float* __restrict__ x,
                                              float* __restrict__ out) {
    const int t    = threadIdx.x;
    const int sub  = t >> 4;                 // 0..15
    const int lane = t & 15;                 // 0..15
    const int cbase = blockIdx.x * 128;

    int  cid[8];
    int  si [8];
    #pragma unroll
    for (int it = 0; it < 8; it++) {
        cid[it] = cbase + it * 16 + sub;
        si [it] = __ldg(&g_sel[cid[it]]);
    }

    float4 v[8];
    #pragma unroll
    for (int it = 0; it < 8; it++) {
        const int row = cid[it] >> 8;        // b*16+g
        const int b   = row >> 4;
        const int g   = row & 15;
        const size_t off = (size_t)b * S_ * C_ + (size_t)si[it] * C_
                         + g * 64 + lane * 4;
        v[it] = *reinterpret_cast<const float4*>(x + off);
    }
    #pragma unroll
    for (int it = 0; it < 8; it++) {
        const int row = cid[it] >> 8;
        const int b   = row >> 4;
        const int g   = row & 15;
        const size_t off = (size_t)b * S_ * C_ + (size_t)si[it] * C_
                         + g * 64 + lane * 4;
        *reinterpret_cast<float4*>(out + off) = v[it];
    }
}

extern "C" void kernel_launch(void* const* d_in, const int* in_sizes, int n_in,
                              void* d_out, int out_size) {
    const float* x = (const float*)d_in[0];
    float* out = (float*)d_out;
    k_norms_zero<<<(B_ * S_) / 8, 256>>>(x, out);
    k_select    <<<B_ * G_, 256>>>();
    k_copy      <<<(B_ * G_ * K_) / 128, 256>>>(x, out);
}